// round 17
// baseline (speedup 1.0000x reference)
#include <cuda_runtime.h>
#include <cuda_fp16.h>
#include <cstdint>

#define MAX_NODES 100000
#define F_DIM     16
#define K_DIM     16
#define OUT_SCALE (1.0f / 128.0f)

// Y node-major: Yn[n][k*16+o] fp16 (51.2 MB). An edge's 4 blocks live in ONE
// 512B row as two 64B chunks 128B apart -> 2 cache lines per edge (was 4).
__device__ __half g_Yn[(size_t)MAX_NODES * 256];

__device__ __forceinline__ float2 h2f(unsigned u) {
    __half2 h = *reinterpret_cast<__half2*>(&u);
    return __half22float2(h);
}
__device__ __forceinline__ unsigned hp2(float a, float b) {
    __half2 h = __floats2half2_rn(a, b);
    return *reinterpret_cast<unsigned*>(&h);
}
__device__ __forceinline__ unsigned hfma2u(unsigned a, unsigned b, unsigned c) {
    __half2 r = __hfma2(*reinterpret_cast<__half2*>(&a),
                        *reinterpret_cast<__half2*>(&b),
                        *reinterpret_cast<__half2*>(&c));
    return *reinterpret_cast<unsigned*>(&r);
}

// ============================================================================
// Stage 1 (HFMA2, node-major out): lane = (k=lane>>1, seg=lane&1) -> warp's 32
// lanes cover one full 512B node row -> coalesced STG.128 in [n][256] layout.
// Warp processes 8 nodes. Per i: 1 W-LDS.128 ([i][k][seg] layout: each 8-lane
// phase covers all 32 banks -> conflict-free) + 4 broadcast x-LDS.64 +
// 32 HFMA2 (86% FMA density).
// ============================================================================
__global__ __launch_bounds__(512)
void stage1_n(const float* __restrict__ x,
              const float* __restrict__ W,
              int n_nodes) {
    __shared__ unsigned wsh[2048];       // 8 KB: [i][k][seg*4+w] = half2 pairs
    __shared__ unsigned xsh[16][128];    // 8 KB: [i][nl] = (x_h, x_h)

    int tid  = threadIdx.x;
    int wid  = tid >> 5;                 // warp -> 8-node group
    int lane = tid & 31;
    int k    = lane >> 1;
    int seg  = lane & 1;
    int node_base = blockIdx.x * 128;

    // W -> half2 pairs in [i][k][op] order: wsh[i*128 + k*8 + op]
#pragma unroll
    for (int e = tid; e < 2048; e += 512) {
        int i  = e >> 7;
        int kk = (e >> 3) & 15;
        int op = e & 7;
        float2 wv = *reinterpret_cast<const float2*>(W + kk * 256 + i * 16 + 2 * op);
        wsh[e] = hp2(wv.x, wv.y);
    }
    // x -> duplicated half2, [i][node_local]
#pragma unroll
    for (int idx = tid; idx < 512; idx += 512) {
        int n = idx >> 2, q = idx & 3;
        int node = min(node_base + n, n_nodes - 1);
        float4 v = reinterpret_cast<const float4*>(x + (size_t)node * 16)[q];
        xsh[4 * q + 0][n] = hp2(v.x, v.x);
        xsh[4 * q + 1][n] = hp2(v.y, v.y);
        xsh[4 * q + 2][n] = hp2(v.z, v.z);
        xsh[4 * q + 3][n] = hp2(v.w, v.w);
    }
    __syncthreads();

    unsigned acc[8][4];                  // 8 nodes x 4 half2 (= 8 outputs)
#pragma unroll
    for (int n = 0; n < 8; n++)
#pragma unroll
        for (int j = 0; j < 4; j++) acc[n][j] = 0u;

    const uint4* wp = reinterpret_cast<const uint4*>(wsh) + (k * 8 + seg * 4) / 4;
    // lane's 16B at word offset k*8 + seg*4 within each i-slab of 128 words
    int nb = wid * 8;

#pragma unroll
    for (int i = 0; i < 16; i++) {
        uint4 wv = reinterpret_cast<const uint4*>(wsh + i * 128 + k * 8 + seg * 4)[0];
        const unsigned* xrow = xsh[i] + nb;
        // broadcast pairs: (x_n, x_{n+1}) via 64-bit reads
        uint2 x01 = *reinterpret_cast<const uint2*>(xrow + 0);
        uint2 x23 = *reinterpret_cast<const uint2*>(xrow + 2);
        uint2 x45 = *reinterpret_cast<const uint2*>(xrow + 4);
        uint2 x67 = *reinterpret_cast<const uint2*>(xrow + 6);

        acc[0][0] = hfma2u(x01.x, wv.x, acc[0][0]);
        acc[0][1] = hfma2u(x01.x, wv.y, acc[0][1]);
        acc[0][2] = hfma2u(x01.x, wv.z, acc[0][2]);
        acc[0][3] = hfma2u(x01.x, wv.w, acc[0][3]);
        acc[1][0] = hfma2u(x01.y, wv.x, acc[1][0]);
        acc[1][1] = hfma2u(x01.y, wv.y, acc[1][1]);
        acc[1][2] = hfma2u(x01.y, wv.z, acc[1][2]);
        acc[1][3] = hfma2u(x01.y, wv.w, acc[1][3]);
        acc[2][0] = hfma2u(x23.x, wv.x, acc[2][0]);
        acc[2][1] = hfma2u(x23.x, wv.y, acc[2][1]);
        acc[2][2] = hfma2u(x23.x, wv.z, acc[2][2]);
        acc[2][3] = hfma2u(x23.x, wv.w, acc[2][3]);
        acc[3][0] = hfma2u(x23.y, wv.x, acc[3][0]);
        acc[3][1] = hfma2u(x23.y, wv.y, acc[3][1]);
        acc[3][2] = hfma2u(x23.y, wv.z, acc[3][2]);
        acc[3][3] = hfma2u(x23.y, wv.w, acc[3][3]);
        acc[4][0] = hfma2u(x45.x, wv.x, acc[4][0]);
        acc[4][1] = hfma2u(x45.x, wv.y, acc[4][1]);
        acc[4][2] = hfma2u(x45.x, wv.z, acc[4][2]);
        acc[4][3] = hfma2u(x45.x, wv.w, acc[4][3]);
        acc[5][0] = hfma2u(x45.y, wv.x, acc[5][0]);
        acc[5][1] = hfma2u(x45.y, wv.y, acc[5][1]);
        acc[5][2] = hfma2u(x45.y, wv.z, acc[5][2]);
        acc[5][3] = hfma2u(x45.y, wv.w, acc[5][3]);
        acc[6][0] = hfma2u(x67.x, wv.x, acc[6][0]);
        acc[6][1] = hfma2u(x67.x, wv.y, acc[6][1]);
        acc[6][2] = hfma2u(x67.x, wv.z, acc[6][2]);
        acc[6][3] = hfma2u(x67.x, wv.w, acc[6][3]);
        acc[7][0] = hfma2u(x67.y, wv.x, acc[7][0]);
        acc[7][1] = hfma2u(x67.y, wv.y, acc[7][1]);
        acc[7][2] = hfma2u(x67.y, wv.z, acc[7][2]);
        acc[7][3] = hfma2u(x67.y, wv.w, acc[7][3]);
    }

    // Stores: per node, warp writes the full 512B row (lane offset = lane*16B)
#pragma unroll
    for (int n = 0; n < 8; n++) {
        int node = node_base + nb + n;
        if (node < n_nodes) {
            uint4* yo = reinterpret_cast<uint4*>(
                g_Yn + (size_t)node * 256 + k * 16 + seg * 8);
            *yo = make_uint4(acc[n][0], acc[n][1], acc[n][2], acc[n][3]);
        }
    }
    (void)wp;
}

// ============================================================================
// Stage 2 (warp-coop, node-major gather): identical butterfly to R12; only
// addressing changes — lane (b,s) reads 16B at row(dj)*512B + k00*32 +
// (b>>1)*128 + (b&1)*32 + s*16 bytes. 2 lines/edge instead of 4.
// ============================================================================
__global__ __launch_bounds__(256)
void stage2_coop(const float2* __restrict__ edge_attr,
                 const int* __restrict__ ei,
                 const int* __restrict__ ej,
                 float* __restrict__ out,
                 int n_nodes, int n_edges) {
    const unsigned FULL = 0xFFFFFFFFu;
    int lane = threadIdx.x & 31;
    int gwarp = (blockIdx.x * 256 + threadIdx.x) >> 5;
    int g = lane >> 3;
    int r = lane & 7;
    int b = r >> 1;
    int s = r & 1;

    int ebase = gwarp * 16;
    if (ebase >= n_edges) return;

    bool keep1 = (b & 1) == 0;
    bool keep2 = (b & 2) == 0;
    // half-offset within the row for this lane's 16B piece
    int lane_off = (b >> 1) * 64 + (b & 1) * 16 + s * 8;   // in halfs

#pragma unroll 1
    for (int it = 0; it < 4; it++) {
        int e = ebase + it * 4 + g;
        bool val = (e < n_edges);
        int eL = val ? e : 0;

        int di = ei[eL];
        int dj = ej[eL];
        float2 at = edge_attr[eL];
        val = val && (di != dj);

        float ux = fminf(fmaxf(at.x, -1.0f), 1.0f);
        float uy = fminf(fmaxf(at.y, -1.0f), 1.0f);
        float vx = (ux + 1.0f) * 1.5f;
        float vy = (uy + 1.0f) * 1.5f;
        int ca = min((int)vx, 2);
        int cb_ = min((int)vy, 2);
        float sx = vx - (float)ca;
        float ty = vy - (float)cb_;
        int k00 = ca * 4 + cb_;

        float cf = ((b & 2) ? sx : (1.0f - sx)) *
                   ((b & 1) ? ty : (1.0f - ty)) * OUT_SCALE;
        if (!val) cf = 0.0f;
        int djs = val ? dj : 0;

        const uint4* p = reinterpret_cast<const uint4*>(
            g_Yn + (size_t)djs * 256 + k00 * 16 + lane_off);
        uint4 Y = *p;

        float2 f0 = h2f(Y.x), f1 = h2f(Y.y), f2 = h2f(Y.z), f3 = h2f(Y.w);
        float m0 = cf * f0.x, m1 = cf * f0.y;
        float m2 = cf * f1.x, m3 = cf * f1.y;
        float m4 = cf * f2.x, m5 = cf * f2.y;
        float m6 = cf * f3.x, m7 = cf * f3.y;

        float s0_ = keep1 ? m4 : m0;
        float s1_ = keep1 ? m5 : m1;
        float s2_ = keep1 ? m6 : m2;
        float s3_ = keep1 ? m7 : m3;
        float p0 = (keep1 ? m0 : m4) + __shfl_xor_sync(FULL, s0_, 2);
        float p1 = (keep1 ? m1 : m5) + __shfl_xor_sync(FULL, s1_, 2);
        float p2 = (keep1 ? m2 : m6) + __shfl_xor_sync(FULL, s2_, 2);
        float p3 = (keep1 ? m3 : m7) + __shfl_xor_sync(FULL, s3_, 2);

        float t0 = keep2 ? p2 : p0;
        float t1 = keep2 ? p3 : p1;
        float q0 = (keep2 ? p0 : p2) + __shfl_xor_sync(FULL, t0, 4);
        float q1 = (keep2 ? p1 : p3) + __shfl_xor_sync(FULL, t1, 4);

        if (val) {
            int idx = s * 8 + (b & 1) * 4 + ((b >> 1) & 1) * 2;
            float* ob = out + (size_t)di * 16 + idx;
            asm volatile("red.global.add.v2.f32 [%0], {%1, %2};"
                         :: "l"(ob), "f"(q0), "f"(q1) : "memory");
        }
    }
}

// Aligns ncu capture (-s 5 -c 1) onto stage1 (4 launches/call)
__global__ void k_dummy() {}

extern "C" void kernel_launch(void* const* d_in, const int* in_sizes, int n_in,
                              void* d_out, int out_size) {
    const float*  x  = (const float*)d_in[0];    // [N, 16] f32
    const float2* ea = (const float2*)d_in[1];   // [E, 2]  f32
    const float*  W  = (const float*)d_in[2];    // [16,16,16] f32
    const int*    ei = (const int*)d_in[3];      // [E] int32
    const int*    ej = (const int*)d_in[4];      // [E] int32
    float* out = (float*)d_out;

    int n_nodes = in_sizes[0] / F_DIM;
    int n_edges = in_sizes[1] / 2;

    cudaMemsetAsync(d_out, 0, (size_t)out_size * sizeof(float), 0);

    stage1_n<<<(n_nodes + 127) / 128, 512>>>(x, W, n_nodes);

    int s2_blocks = (n_edges + 127) / 128;
    stage2_coop<<<s2_blocks, 256>>>(ea, ei, ej, out, n_nodes, n_edges);
    k_dummy<<<1, 32>>>();
}